// round 1
// baseline (speedup 1.0000x reference)
#include <cuda_runtime.h>

#define KK   4
#define Bb   32768
#define NNn  10
#define E1   90

// Output layout (flattened tuple, float32):
//   k_ij (4,32768,10,10) | a_ik (4,32768,10) | t_j (4,32768,10) | R (4,32768,10,10) | R_t (...)
#define SZ_KIJ  13107200
#define SZ_AIK  1310720
#define OFF_KIJ 0
#define OFF_AIK 13107200
#define OFF_TJ  14417920
#define OFF_R   15728640
#define OFF_RT  28835840

static __device__ __forceinline__ int eidx(int i, int j) {
    // edge (i -> j), i != j, enumeration: for i: for j != i
    return i * 9 + j - (j > i ? 1 : 0);
}

__global__ __launch_bounds__(128) void gnn_kernel(
    const float* __restrict__ x,
    const float* __restrict__ ew,
    const float* __restrict__ eigen,
    const float* __restrict__ a0p,
    const float* __restrict__ W0,
    const float* __restrict__ b0,
    const float* __restrict__ W1,
    const float* __restrict__ b1,
    const float* __restrict__ bp,
    const float* __restrict__ cp,
    const float* __restrict__ ww,
    float* __restrict__ out)
{
    const int b = blockIdx.x;
    const int tid = threadIdx.x;

    __shared__ float s_w[KK][E1];
    __shared__ float s_dinv[KK][NNn];
    __shared__ float s_A[KK][NNn][NNn];     // A[k][src][dst] = norm(src->dst)
    __shared__ float s_hA[KK][NNn][16];
    __shared__ float s_hB[KK][NNn][16];
    __shared__ float s_y[KK][NNn][8];
    __shared__ float s_yw[KK][NNn][8];
    __shared__ float s_pm[KK][NNn];
    __shared__ float s_tk[KK][NNn];
    __shared__ float s_eig[KK];
    __shared__ float s_W0[192];
    __shared__ float s_W1[512];
    __shared__ float s_b0[16];
    __shared__ float s_b1[8];
    __shared__ float s_bp[8];
    __shared__ float s_cp[8];
    __shared__ float s_ww[64];
    __shared__ float s_a0;

    // ---- stage parameters (same for all blocks -> L1/L2 hits) ----
    for (int i = tid; i < 192; i += 128) s_W0[i] = W0[i];
    for (int i = tid; i < 512; i += 128) s_W1[i] = W1[i];
    if (tid < 16)                s_b0[tid]      = b0[tid];
    else if (tid < 24)           s_b1[tid - 16] = b1[tid - 16];
    else if (tid < 32)           s_bp[tid - 24] = bp[tid - 24];
    else if (tid < 40)           s_cp[tid - 32] = cp[tid - 32];
    else if (tid == 40)          s_a0           = a0p[0];
    else if (tid >= 44 && tid < 48) s_eig[tid - 44] = eigen[(tid - 44) * Bb + b];
    if (tid >= 64) s_ww[tid - 64] = ww[tid - 64];

    // ---- edge weights (4 groups x 90, contiguous per group) ----
    for (int idx = tid; idx < KK * E1; idx += 128) {
        int k = idx / E1, e = idx % E1;
        s_w[k][e] = ew[(k * Bb + b) * E1 + e];
    }
    // ---- x (4 groups x 10 nodes x 3 feats, contiguous per group) ----
    for (int idx = tid; idx < 120; idx += 128) {
        int k = idx / 30, r = idx % 30;
        float v = x[(k * Bb + b) * 30 + r];
        int j = r / 3, c = r % 3;
        s_hA[k][j][c] = v;
        if (c == 2) s_pm[k][j] = fmaxf(v, 0.0f);
    }
    __syncthreads();

    // ---- degree (incoming) + dinv ----
    if (tid < 40) {
        int k = tid / 10, j = tid % 10;
        float d = 0.f;
        #pragma unroll
        for (int i = 0; i < 10; i++)
            if (i != j) d += s_w[k][eidx(i, j)];
        s_dinv[k][j] = (d > 0.f) ? rsqrtf(d) : 0.f;
    }
    __syncthreads();

    // ---- normalized adjacency + R / R_t outputs ----
    #pragma unroll
    for (int it = 0; it < 4; it++) {
        int idx = tid + it * 128;
        if (idx < 400) {
            int k = idx / 100, r = idx % 100;
            int n = r / 10, m = r % 10;
            float wnm = (n == m) ? 0.f : s_w[k][eidx(n, m)];
            float wmn = (n == m) ? 0.f : s_w[k][eidx(m, n)];
            s_A[k][n][m] = wnm * s_dinv[k][n] * s_dinv[k][m];
            float e = s_eig[k];
            int g = k * Bb + b;
            out[OFF_R  + g * 100 + r] = wnm * e;
            out[OFF_RT + g * 100 + r] = wmn * e;
        }
    }
    __syncthreads();

    // ================= TAGConv layer 1 (F_IN=3 -> F_H=16) =================
    float acc1[5];
    #pragma unroll
    for (int it = 0; it < 5; it++) {
        int idx = tid + it * 128;
        int k = idx / 160, j = (idx / 16) % 10, f = idx % 16;
        const float* hv = s_hA[k][j];
        acc1[it] = hv[0] * s_W0[f] + hv[1] * s_W0[16 + f] + hv[2] * s_W0[32 + f];
    }
    {
        float (*cur)[NNn][16] = s_hA;
        float (*nxt)[NNn][16] = s_hB;
        #pragma unroll
        for (int hk = 1; hk <= 3; hk++) {
            if (tid < 120) {
                int k = tid / 30, j = (tid / 3) % 10, c = tid % 3;
                float s = 0.f;
                #pragma unroll
                for (int i = 0; i < 10; i++) s += s_A[k][i][j] * cur[k][i][c];
                nxt[k][j][c] = s;
            }
            __syncthreads();
            const float* Wp = &s_W0[hk * 48];
            #pragma unroll
            for (int it = 0; it < 5; it++) {
                int idx = tid + it * 128;
                int k = idx / 160, j = (idx / 16) % 10, f = idx % 16;
                const float* hv = nxt[k][j];
                acc1[it] += hv[0] * Wp[f] + hv[1] * Wp[16 + f] + hv[2] * Wp[32 + f];
            }
            float (*t)[NNn][16] = cur; cur = nxt; nxt = t;
        }
    }
    // y1 = leaky_relu(acc + b0) -> s_hA (input of layer 2)
    #pragma unroll
    for (int it = 0; it < 5; it++) {
        int idx = tid + it * 128;
        int k = idx / 160, j = (idx / 16) % 10, f = idx % 16;
        float v = acc1[it] + s_b0[f];
        s_hA[k][j][f] = (v >= 0.f) ? v : 0.01f * v;
    }
    __syncthreads();

    // ================= TAGConv layer 2 (F_H=16 -> F_OUT=8) =================
    float acc2[3] = {0.f, 0.f, 0.f};
    #pragma unroll
    for (int it = 0; it < 3; it++) {
        int idx = tid + it * 128;
        if (idx < 320) {
            int k = idx / 80, j = (idx / 8) % 10, f = idx % 8;
            const float* hv = s_hA[k][j];
            float s = 0.f;
            #pragma unroll
            for (int c = 0; c < 16; c++) s += hv[c] * s_W1[c * 8 + f];
            acc2[it] = s;
        }
    }
    {
        float (*cur)[NNn][16] = s_hA;
        float (*nxt)[NNn][16] = s_hB;
        #pragma unroll
        for (int hk = 1; hk <= 3; hk++) {
            #pragma unroll
            for (int it = 0; it < 5; it++) {
                int idx = tid + it * 128;
                int k = idx / 160, j = (idx / 16) % 10, c = idx % 16;
                float s = 0.f;
                #pragma unroll
                for (int i = 0; i < 10; i++) s += s_A[k][i][j] * cur[k][i][c];
                nxt[k][j][c] = s;
            }
            __syncthreads();
            const float* Wp = &s_W1[hk * 128];
            #pragma unroll
            for (int it = 0; it < 3; it++) {
                int idx = tid + it * 128;
                if (idx < 320) {
                    int k = idx / 80, j = (idx / 8) % 10, f = idx % 8;
                    const float* hv = nxt[k][j];
                    float s = acc2[it];
                    #pragma unroll
                    for (int c = 0; c < 16; c++) s += hv[c] * Wp[c * 8 + f];
                    acc2[it] = s;
                }
            }
            float (*t)[NNn][16] = cur; cur = nxt; nxt = t;
        }
    }
    // y = leaky_relu(acc2 + b1) -> s_y
    #pragma unroll
    for (int it = 0; it < 3; it++) {
        int idx = tid + it * 128;
        if (idx < 320) {
            int k = idx / 80, j = (idx / 8) % 10, f = idx % 8;
            float v = acc2[it] + s_b1[f];
            s_y[k][j][f] = (v >= 0.f) ? v : 0.01f * v;
        }
    }
    __syncthreads();

    // ================= epilogue =================
    // yw = y @ w_w.T
    #pragma unroll
    for (int it = 0; it < 3; it++) {
        int idx = tid + it * 128;
        if (idx < 320) {
            int k = idx / 80, j = (idx / 8) % 10, d = idx % 8;
            const float* yv = s_y[k][j];
            float s = 0.f;
            #pragma unroll
            for (int e = 0; e < 8; e++) s += yv[e] * s_ww[d * 8 + e];
            s_yw[k][j][d] = s;
        }
    }
    // a_ik, t_k
    if (tid < 40) {
        int k = tid / 10, j = tid % 10;
        const float* yv = s_y[k][j];
        float ay = 0.f, ty = 0.f;
        #pragma unroll
        for (int f = 0; f < 8; f++) { ay += yv[f] * s_bp[f]; ty += yv[f] * s_cp[f]; }
        out[OFF_AIK + (k * Bb + b) * 10 + j] = s_a0 + fmaxf(ay, 0.f);
        float tk = ty * (1.0f - s_pm[k][j]);
        if (tk == 0.0f) tk = -10000000000.0f;
        s_tk[k][j] = tk;
    }
    __syncthreads();

    // t_j = softmax over K
    if (tid < 10) {
        float t0 = s_tk[0][tid], t1 = s_tk[1][tid], t2 = s_tk[2][tid], t3 = s_tk[3][tid];
        float m = fmaxf(fmaxf(t0, t1), fmaxf(t2, t3));
        float e0 = expf(t0 - m), e1 = expf(t1 - m), e2 = expf(t2 - m), e3 = expf(t3 - m);
        float inv = 1.f / (e0 + e1 + e2 + e3);
        out[OFF_TJ + (0 * Bb + b) * 10 + tid] = e0 * inv;
        out[OFF_TJ + (1 * Bb + b) * 10 + tid] = e1 * inv;
        out[OFF_TJ + (2 * Bb + b) * 10 + tid] = e2 * inv;
        out[OFF_TJ + (3 * Bb + b) * 10 + tid] = e3 * inv;
    }

    // K_y + softmax over K -> k_ij
    if (tid < 100) {
        int n = tid / 10, m = tid % 10;
        float kv[4];
        #pragma unroll
        for (int k = 0; k < 4; k++) {
            const float* a = s_yw[k][n];
            const float* c = s_y[k][m];
            float s = 0.f;
            #pragma unroll
            for (int d = 0; d < 8; d++) s += a[d] * c[d];
            kv[k] = s;
        }
        float mx = fmaxf(fmaxf(kv[0], kv[1]), fmaxf(kv[2], kv[3]));
        float e[4];
        float ssum = 0.f;
        #pragma unroll
        for (int k = 0; k < 4; k++) { e[k] = expf(kv[k] - mx); ssum += e[k]; }
        float inv = 1.f / ssum;
        #pragma unroll
        for (int k = 0; k < 4; k++)
            out[OFF_KIJ + (k * Bb + b) * 100 + tid] = e[k] * inv;
    }
}

extern "C" void kernel_launch(void* const* d_in, const int* in_sizes, int n_in,
                              void* d_out, int out_size) {
    (void)out_size;
    const float* x  = (const float*)d_in[0];
    // d_in[1] = edge_index (fixed pattern, unused)
    const float* ew = (const float*)d_in[2];
    // Skip scalar ints K, batch_size, N if the harness passes them
    int base = 3;
    if (n_in >= 15 && in_sizes[3] == 1 && in_sizes[4] == 1 && in_sizes[5] == 1) base = 6;
    const float* eigen = (const float*)d_in[base + 0];
    const float* a0    = (const float*)d_in[base + 1];
    const float* W0    = (const float*)d_in[base + 2];
    const float* b0    = (const float*)d_in[base + 3];
    const float* W1    = (const float*)d_in[base + 4];
    const float* b1    = (const float*)d_in[base + 5];
    const float* bp    = (const float*)d_in[base + 6];
    const float* cp    = (const float*)d_in[base + 7];
    const float* ww    = (const float*)d_in[base + 8];

    gnn_kernel<<<Bb, 128>>>(x, ew, eigen, a0, W0, b0, W1, b1, bp, cp, ww, (float*)d_out);
}

// round 2
// speedup vs baseline: 1.1128x; 1.1128x over previous
#include <cuda_runtime.h>

#define KK 4
#define Bb 32768

#define OFF_KIJ 0
#define OFF_AIK 13107200
#define OFF_TJ  14417920
#define OFF_R   15728640
#define OFF_RT  28835840

static __device__ __forceinline__ int eidx(int i, int j) {
    return i * 9 + j - (j > i ? 1 : 0);
}
static __device__ __forceinline__ float4 f4fma(float a, float4 w, float4 acc) {
    acc.x = fmaf(a, w.x, acc.x);
    acc.y = fmaf(a, w.y, acc.y);
    acc.z = fmaf(a, w.z, acc.z);
    acc.w = fmaf(a, w.w, acc.w);
    return acc;
}
static __device__ __forceinline__ float dot4(float4 a, float4 b) {
    return a.x*b.x + a.y*b.y + a.z*b.z + a.w*b.w;
}
static __device__ __forceinline__ float lrelu(float v) {
    return v >= 0.f ? v : 0.01f * v;
}

__global__ __launch_bounds__(128) void gnn_kernel(
    const float* __restrict__ x,
    const float* __restrict__ ew,
    const float* __restrict__ eigen,
    const float* __restrict__ a0p,
    const float* __restrict__ W0,
    const float* __restrict__ b0,
    const float* __restrict__ W1,
    const float* __restrict__ b1,
    const float* __restrict__ bp,
    const float* __restrict__ cp,
    const float* __restrict__ ww,
    float* __restrict__ out)
{
    const int b = blockIdx.x;
    const int tid = threadIdx.x;

    __shared__ float s_w[KK][90];
    __shared__ float s_dinv[KK][10];
    __shared__ float s_A[KK][10][10];
    __shared__ __align__(16) float s_hA[KK][10][16];
    __shared__ __align__(16) float s_hB[KK][10][16];
    __shared__ __align__(16) float s_y[KK][10][8];
    __shared__ __align__(16) float s_yw[KK][10][8];
    __shared__ float s_pm[KK][10];
    __shared__ float s_tk[KK][10];
    __shared__ float s_eig[KK];
    __shared__ __align__(16) float s_W0[192];
    __shared__ __align__(16) float s_W1[512];
    __shared__ __align__(16) float s_b0[16];
    __shared__ __align__(16) float s_b1[8];
    __shared__ __align__(16) float s_bp[8];
    __shared__ __align__(16) float s_cp[8];
    __shared__ __align__(16) float s_ww[64];
    __shared__ float s_a0;

    // ---- stage parameters ----
    for (int i = tid; i < 192; i += 128) s_W0[i] = W0[i];
    for (int i = tid; i < 512; i += 128) s_W1[i] = W1[i];
    if (tid < 16)                   s_b0[tid]      = b0[tid];
    else if (tid < 24)              s_b1[tid - 16] = b1[tid - 16];
    else if (tid < 32)              s_bp[tid - 24] = bp[tid - 24];
    else if (tid < 40)              s_cp[tid - 32] = cp[tid - 32];
    else if (tid == 40)             s_a0           = a0p[0];
    else if (tid >= 44 && tid < 48) s_eig[tid - 44] = eigen[(tid - 44) * Bb + b];
    if (tid >= 64) s_ww[tid - 64] = ww[tid - 64];

    for (int idx = tid; idx < 360; idx += 128) {
        int k = idx / 90, e = idx % 90;
        s_w[k][e] = ew[(k * Bb + b) * 90 + e];
    }
    for (int idx = tid; idx < 120; idx += 128) {
        int k = idx / 30, r = idx % 30;
        float v = x[(k * Bb + b) * 30 + r];
        int j = r / 3, c = r % 3;
        s_hA[k][j][c] = v;
        if (c == 2) s_pm[k][j] = fmaxf(v, 0.0f);
    }
    __syncthreads();

    // ---- degree + dinv ----
    if (tid < 40) {
        int k = tid / 10, j = tid % 10;
        float d = 0.f;
        #pragma unroll
        for (int i = 0; i < 10; i++)
            if (i != j) d += s_w[k][eidx(i, j)];
        s_dinv[k][j] = (d > 0.f) ? rsqrtf(d) : 0.f;
    }
    __syncthreads();

    // ---- normalized adjacency + R / R_t ----
    #pragma unroll
    for (int it = 0; it < 4; it++) {
        int idx = tid + it * 128;
        if (idx < 400) {
            int k = idx / 100, r = idx % 100;
            int n = r / 10, m = r % 10;
            float wnm = (n == m) ? 0.f : s_w[k][eidx(n, m)];
            float wmn = (n == m) ? 0.f : s_w[k][eidx(m, n)];
            s_A[k][n][m] = wnm * s_dinv[k][n] * s_dinv[k][m];
            float e = s_eig[k];
            int g = k * Bb + b;
            out[OFF_R  + g * 100 + r] = wnm * e;
            out[OFF_RT + g * 100 + r] = wmn * e;
        }
    }
    __syncthreads();

    // ---- mapping A: 160 items (k, j, feature-quad) ----
    const int q    = tid & 3;
    const int a0_k = tid / 40;
    const int a0_j = (tid % 40) >> 2;
    const bool hasA1 = (tid < 32);
    const int a1_j = 2 + (tid >> 2);   // item idx = 128+tid -> k=3

    // ================= TAGConv layer 1 (3 -> 16) =================
    const float4* W0v = reinterpret_cast<const float4*>(s_W0);
    float4 acc1a = make_float4(0.f, 0.f, 0.f, 0.f);
    float4 acc1b = make_float4(0.f, 0.f, 0.f, 0.f);
    {
        const float* hv = s_hA[a0_k][a0_j];
        acc1a = f4fma(hv[0], W0v[q],     acc1a);
        acc1a = f4fma(hv[1], W0v[4 + q], acc1a);
        acc1a = f4fma(hv[2], W0v[8 + q], acc1a);
        if (hasA1) {
            const float* hv1 = s_hA[3][a1_j];
            acc1b = f4fma(hv1[0], W0v[q],     acc1b);
            acc1b = f4fma(hv1[1], W0v[4 + q], acc1b);
            acc1b = f4fma(hv1[2], W0v[8 + q], acc1b);
        }
    }
    {
        float (*cur)[10][16] = s_hA;
        float (*nxt)[10][16] = s_hB;
        #pragma unroll
        for (int hk = 1; hk <= 3; hk++) {
            if (tid < 120) {
                int k = tid / 30, rem = tid % 30, j = rem / 3, c = rem % 3;
                float s = 0.f;
                #pragma unroll
                for (int i = 0; i < 10; i++) s = fmaf(s_A[k][i][j], cur[k][i][c], s);
                nxt[k][j][c] = s;
            }
            __syncthreads();
            const float* hv = nxt[a0_k][a0_j];
            acc1a = f4fma(hv[0], W0v[hk * 12 + q],     acc1a);
            acc1a = f4fma(hv[1], W0v[hk * 12 + 4 + q], acc1a);
            acc1a = f4fma(hv[2], W0v[hk * 12 + 8 + q], acc1a);
            if (hasA1) {
                const float* hv1 = nxt[3][a1_j];
                acc1b = f4fma(hv1[0], W0v[hk * 12 + q],     acc1b);
                acc1b = f4fma(hv1[1], W0v[hk * 12 + 4 + q], acc1b);
                acc1b = f4fma(hv1[2], W0v[hk * 12 + 8 + q], acc1b);
            }
            float (*t)[10][16] = cur; cur = nxt; nxt = t;
        }
    }
    // leaky_relu(acc + b0) -> s_hA (layer-2 input)
    {
        float4 bb = reinterpret_cast<const float4*>(s_b0)[q];
        float4 v = make_float4(lrelu(acc1a.x + bb.x), lrelu(acc1a.y + bb.y),
                               lrelu(acc1a.z + bb.z), lrelu(acc1a.w + bb.w));
        reinterpret_cast<float4*>(s_hA[a0_k][a0_j])[q] = v;
        if (hasA1) {
            float4 v1 = make_float4(lrelu(acc1b.x + bb.x), lrelu(acc1b.y + bb.y),
                                    lrelu(acc1b.z + bb.z), lrelu(acc1b.w + bb.w));
            reinterpret_cast<float4*>(s_hA[3][a1_j])[q] = v1;
        }
    }
    __syncthreads();

    // ================= TAGConv layer 2 (16 -> 8) =================
    const int bk = tid / 20, brem = tid % 20, bj = brem >> 1, bg = brem & 1;
    const bool hasB = (tid < 80);
    const float4* W1v = reinterpret_cast<const float4*>(s_W1);
    float4 acc2 = make_float4(0.f, 0.f, 0.f, 0.f);
    if (hasB) {
        const float4* hv4 = reinterpret_cast<const float4*>(s_hA[bk][bj]);
        #pragma unroll
        for (int cq = 0; cq < 4; cq++) {
            float4 h = hv4[cq];
            acc2 = f4fma(h.x, W1v[(cq * 4 + 0) * 2 + bg], acc2);
            acc2 = f4fma(h.y, W1v[(cq * 4 + 1) * 2 + bg], acc2);
            acc2 = f4fma(h.z, W1v[(cq * 4 + 2) * 2 + bg], acc2);
            acc2 = f4fma(h.w, W1v[(cq * 4 + 3) * 2 + bg], acc2);
        }
    }
    // preload A column for item A0 (reused over 3 hops)
    float acol[10];
    #pragma unroll
    for (int i = 0; i < 10; i++) acol[i] = s_A[a0_k][i][a0_j];

    {
        float (*cur)[10][16] = s_hA;
        float (*nxt)[10][16] = s_hB;
        #pragma unroll
        for (int hk = 1; hk <= 3; hk++) {
            {
                float4 s = make_float4(0.f, 0.f, 0.f, 0.f);
                #pragma unroll
                for (int i = 0; i < 10; i++) {
                    float4 hv = reinterpret_cast<const float4*>(cur[a0_k][i])[q];
                    s = f4fma(acol[i], hv, s);
                }
                reinterpret_cast<float4*>(nxt[a0_k][a0_j])[q] = s;
                if (hasA1) {
                    float4 s1 = make_float4(0.f, 0.f, 0.f, 0.f);
                    #pragma unroll
                    for (int i = 0; i < 10; i++) {
                        float4 hv = reinterpret_cast<const float4*>(cur[3][i])[q];
                        s1 = f4fma(s_A[3][i][a1_j], hv, s1);
                    }
                    reinterpret_cast<float4*>(nxt[3][a1_j])[q] = s1;
                }
            }
            __syncthreads();
            if (hasB) {
                const float4* hv4 = reinterpret_cast<const float4*>(nxt[bk][bj]);
                #pragma unroll
                for (int cq = 0; cq < 4; cq++) {
                    float4 h = hv4[cq];
                    acc2 = f4fma(h.x, W1v[hk * 32 + (cq * 4 + 0) * 2 + bg], acc2);
                    acc2 = f4fma(h.y, W1v[hk * 32 + (cq * 4 + 1) * 2 + bg], acc2);
                    acc2 = f4fma(h.z, W1v[hk * 32 + (cq * 4 + 2) * 2 + bg], acc2);
                    acc2 = f4fma(h.w, W1v[hk * 32 + (cq * 4 + 3) * 2 + bg], acc2);
                }
            }
            float (*t)[10][16] = cur; cur = nxt; nxt = t;
        }
    }
    // y = leaky_relu(acc2 + b1) -> s_y
    if (hasB) {
        float4 bb = reinterpret_cast<const float4*>(s_b1)[bg];
        float4 v = make_float4(lrelu(acc2.x + bb.x), lrelu(acc2.y + bb.y),
                               lrelu(acc2.z + bb.z), lrelu(acc2.w + bb.w));
        reinterpret_cast<float4*>(s_y[bk][bj])[bg] = v;
    }
    __syncthreads();

    // ================= epilogue =================
    // yw = y @ w_w.T (quad of d per thread)
    if (hasB) {
        const float4* yv = reinterpret_cast<const float4*>(s_y[bk][bj]);
        float4 y0 = yv[0], y1 = yv[1];
        const float4* wwv = reinterpret_cast<const float4*>(s_ww);
        float4 r;
        {
            int d = bg * 4;
            r.x = dot4(y0, wwv[(d + 0) * 2]) + dot4(y1, wwv[(d + 0) * 2 + 1]);
            r.y = dot4(y0, wwv[(d + 1) * 2]) + dot4(y1, wwv[(d + 1) * 2 + 1]);
            r.z = dot4(y0, wwv[(d + 2) * 2]) + dot4(y1, wwv[(d + 2) * 2 + 1]);
            r.w = dot4(y0, wwv[(d + 3) * 2]) + dot4(y1, wwv[(d + 3) * 2 + 1]);
        }
        reinterpret_cast<float4*>(s_yw[bk][bj])[bg] = r;
    }
    // a_ik, t_k
    if (tid < 40) {
        int k = tid / 10, j = tid % 10;
        const float4* yv = reinterpret_cast<const float4*>(s_y[k][j]);
        float4 y0 = yv[0], y1 = yv[1];
        const float4* bpv = reinterpret_cast<const float4*>(s_bp);
        const float4* cpv = reinterpret_cast<const float4*>(s_cp);
        float ay = dot4(y0, bpv[0]) + dot4(y1, bpv[1]);
        float ty = dot4(y0, cpv[0]) + dot4(y1, cpv[1]);
        out[OFF_AIK + (k * Bb + b) * 10 + j] = s_a0 + fmaxf(ay, 0.f);
        float tk = ty * (1.0f - s_pm[k][j]);
        if (tk == 0.0f) tk = -10000000000.0f;
        s_tk[k][j] = tk;
    }
    __syncthreads();

    // t_j = softmax over K
    if (tid < 10) {
        float t0 = s_tk[0][tid], t1 = s_tk[1][tid], t2 = s_tk[2][tid], t3 = s_tk[3][tid];
        float m = fmaxf(fmaxf(t0, t1), fmaxf(t2, t3));
        float e0 = __expf(t0 - m), e1 = __expf(t1 - m);
        float e2 = __expf(t2 - m), e3 = __expf(t3 - m);
        float inv = 1.f / (e0 + e1 + e2 + e3);
        out[OFF_TJ + (0 * Bb + b) * 10 + tid] = e0 * inv;
        out[OFF_TJ + (1 * Bb + b) * 10 + tid] = e1 * inv;
        out[OFF_TJ + (2 * Bb + b) * 10 + tid] = e2 * inv;
        out[OFF_TJ + (3 * Bb + b) * 10 + tid] = e3 * inv;
    }

    // K_y + softmax over K -> k_ij
    if (tid < 100) {
        int n = tid / 10, m = tid % 10;
        float kv[4];
        #pragma unroll
        for (int k = 0; k < 4; k++) {
            const float4* av = reinterpret_cast<const float4*>(s_yw[k][n]);
            const float4* cv = reinterpret_cast<const float4*>(s_y[k][m]);
            kv[k] = dot4(av[0], cv[0]) + dot4(av[1], cv[1]);
        }
        float mx = fmaxf(fmaxf(kv[0], kv[1]), fmaxf(kv[2], kv[3]));
        float e[4];
        float ssum = 0.f;
        #pragma unroll
        for (int k = 0; k < 4; k++) { e[k] = __expf(kv[k] - mx); ssum += e[k]; }
        float inv = 1.f / ssum;
        #pragma unroll
        for (int k = 0; k < 4; k++)
            out[OFF_KIJ + (k * Bb + b) * 100 + tid] = e[k] * inv;
    }
}

extern "C" void kernel_launch(void* const* d_in, const int* in_sizes, int n_in,
                              void* d_out, int out_size) {
    (void)out_size;
    const float* x  = (const float*)d_in[0];
    const float* ew = (const float*)d_in[2];
    int base = 3;
    if (n_in >= 15 && in_sizes[3] == 1 && in_sizes[4] == 1 && in_sizes[5] == 1) base = 6;
    const float* eigen = (const float*)d_in[base + 0];
    const float* a0    = (const float*)d_in[base + 1];
    const float* W0    = (const float*)d_in[base + 2];
    const float* b0    = (const float*)d_in[base + 3];
    const float* W1    = (const float*)d_in[base + 4];
    const float* b1    = (const float*)d_in[base + 5];
    const float* bp    = (const float*)d_in[base + 6];
    const float* cp    = (const float*)d_in[base + 7];
    const float* ww    = (const float*)d_in[base + 8];

    gnn_kernel<<<Bb, 128>>>(x, ew, eigen, a0, W0, b0, W1, b1, bp, cp, ww, (float*)d_out);
}

// round 4
// speedup vs baseline: 1.5618x; 1.4034x over previous
#include <cuda_runtime.h>

#define Bb 32768

#define OFF_KIJ 0
#define OFF_AIK 13107200
#define OFF_TJ  14417920
#define OFF_R   15728640
#define OFF_RT  28835840

static __device__ __forceinline__ int eidx(int i, int j) {
    return i * 9 + j - (j > i ? 1 : 0);
}
static __device__ __forceinline__ float4 f4fma(float a, float4 w, float4 acc) {
    acc.x = fmaf(a, w.x, acc.x);
    acc.y = fmaf(a, w.y, acc.y);
    acc.z = fmaf(a, w.z, acc.z);
    acc.w = fmaf(a, w.w, acc.w);
    return acc;
}
static __device__ __forceinline__ float dot4(float4 a, float4 b) {
    return a.x*b.x + a.y*b.y + a.z*b.z + a.w*b.w;
}
static __device__ __forceinline__ float lrelu(float v) {
    return v >= 0.f ? v : 0.01f * v;
}
// acc += (16-vec y) dot (16x4 slab of W1), W1 quads at base, stride 2 per c
static __device__ __forceinline__ float4 proj16(const float4* __restrict__ Wq, int base,
                                                float4 y0, float4 y1, float4 y2, float4 y3,
                                                float4 acc) {
    acc = f4fma(y0.x, Wq[base + 0],  acc);
    acc = f4fma(y0.y, Wq[base + 2],  acc);
    acc = f4fma(y0.z, Wq[base + 4],  acc);
    acc = f4fma(y0.w, Wq[base + 6],  acc);
    acc = f4fma(y1.x, Wq[base + 8],  acc);
    acc = f4fma(y1.y, Wq[base + 10], acc);
    acc = f4fma(y1.z, Wq[base + 12], acc);
    acc = f4fma(y1.w, Wq[base + 14], acc);
    acc = f4fma(y2.x, Wq[base + 16], acc);
    acc = f4fma(y2.y, Wq[base + 18], acc);
    acc = f4fma(y2.z, Wq[base + 20], acc);
    acc = f4fma(y2.w, Wq[base + 22], acc);
    acc = f4fma(y3.x, Wq[base + 24], acc);
    acc = f4fma(y3.y, Wq[base + 26], acc);
    acc = f4fma(y3.z, Wq[base + 28], acc);
    acc = f4fma(y3.w, Wq[base + 30], acc);
    return acc;
}

// word-offset helpers
#define SXW(h,k,j)  ((((h)*4+(k))*10+(j))*4)    // s_x  [hop][k][j][4]
#define Y1W(k,j)    ((k)*200+(j)*20)            // s_Y1 [k][j][20] (16 used)
#define ZW(k,j)     ((k)*120+(j)*12)            // s_z  [k][j][12] (8 used)

__global__ __launch_bounds__(128) void gnn_kernel(
    const float* __restrict__ x,
    const float* __restrict__ ew,
    const float* __restrict__ eigen,
    const float* __restrict__ a0p,
    const float* __restrict__ W0,
    const float* __restrict__ b0,
    const float* __restrict__ W1,
    const float* __restrict__ b1,
    const float* __restrict__ bp,
    const float* __restrict__ cp,
    const float* __restrict__ ww,
    float* __restrict__ out)
{
    const int b = blockIdx.x;
    const int tid = threadIdx.x;

    __shared__ float s_w[4][90];
    __shared__ float s_dinv[4][10];
    __shared__ float s_A[4][10][10];
    __shared__ __align__(16) float s_x[640];    // hop-propagated inputs (3-wide, padded to 4)
    __shared__ __align__(16) float s_Y1[800];   // layer-1 output, rows padded to 20
    __shared__ __align__(16) float s_zA[480];   // Horner state ping
    __shared__ __align__(16) float s_zB[480];   // Horner state pong
    __shared__ __align__(16) float s_y[4][10][8];
    __shared__ __align__(16) float s_yw[4][10][8];
    __shared__ float s_pm[4][10];
    __shared__ float s_tk[4][10];
    __shared__ float s_eig[4];
    __shared__ __align__(16) float s_W0[192];   // [hop][3][16]
    __shared__ __align__(16) float s_W1[512];   // [hop][16][8]
    __shared__ __align__(16) float s_b0[16];
    __shared__ __align__(16) float s_b1[8];
    __shared__ __align__(16) float s_bp[8];
    __shared__ __align__(16) float s_cp[8];
    __shared__ __align__(16) float s_ww[64];
    __shared__ float s_a0;

    // ---- stage parameters ----
    for (int i = tid; i < 192; i += 128) s_W0[i] = W0[i];
    for (int i = tid; i < 512; i += 128) s_W1[i] = W1[i];
    if (tid < 16)                   s_b0[tid]      = b0[tid];
    else if (tid < 24)              s_b1[tid - 16] = b1[tid - 16];
    else if (tid < 32)              s_bp[tid - 24] = bp[tid - 24];
    else if (tid < 40)              s_cp[tid - 32] = cp[tid - 32];
    else if (tid == 40)             s_a0           = a0p[0];
    else if (tid >= 44 && tid < 48) s_eig[tid - 44] = eigen[(tid - 44) * Bb + b];
    if (tid >= 64) s_ww[tid - 64] = ww[tid - 64];

    for (int idx = tid; idx < 360; idx += 128) {
        int k = idx / 90, e = idx % 90;
        s_w[k][e] = ew[(k * Bb + b) * 90 + e];
    }
    for (int idx = tid; idx < 120; idx += 128) {
        int k = idx / 30, r = idx % 30;
        float v = x[(k * Bb + b) * 30 + r];
        int j = r / 3, c = r % 3;
        s_x[(k * 10 + j) * 4 + c] = v;     // hop 0
        if (c == 2) s_pm[k][j] = fmaxf(v, 0.0f);
    }
    __syncthreads();

    // ---- degree + dinv ----
    if (tid < 40) {
        int k = tid / 10, j = tid % 10;
        float d = 0.f;
        #pragma unroll
        for (int i = 0; i < 10; i++)
            if (i != j) d += s_w[k][eidx(i, j)];
        s_dinv[k][j] = (d > 0.f) ? rsqrtf(d) : 0.f;
    }
    __syncthreads();

    // ---- normalized adjacency + R / R_t ----
    #pragma unroll
    for (int it = 0; it < 4; it++) {
        int idx = tid + it * 128;
        if (idx < 400) {
            int k = idx / 100, r = idx % 100;
            int n = r / 10, m = r % 10;
            float wnm = (n == m) ? 0.f : s_w[k][eidx(n, m)];
            float wmn = (n == m) ? 0.f : s_w[k][eidx(m, n)];
            s_A[k][n][m] = wnm * s_dinv[k][n] * s_dinv[k][m];
            float e = s_eig[k];
            int g = k * Bb + b;
            out[OFF_R  + g * 100 + r] = wnm * e;
            out[OFF_RT + g * 100 + r] = wmn * e;
        }
    }
    __syncthreads();

    // ================= layer-1 hop propagation (3-wide) =================
    // 120 threads: (k1, j1, c1); A column cached in registers across hops
    const int k1 = tid / 30;
    const int r1 = tid % 30;
    const int j1 = r1 / 3;
    const int c1 = r1 % 3;
    float acol1[10];
    if (tid < 120) {
        #pragma unroll
        for (int i = 0; i < 10; i++) acol1[i] = s_A[k1][i][j1];
    }
    #pragma unroll
    for (int hk = 0; hk < 3; hk++) {
        if (tid < 120) {
            const float* src = &s_x[SXW(hk, k1, 0) + c1];
            float s = 0.f;
            #pragma unroll
            for (int i = 0; i < 10; i++) s = fmaf(acol1[i], src[i * 4], s);
            s_x[SXW(hk + 1, k1, j1) + c1] = s;
        }
        __syncthreads();
    }

    // ---- common 80-thread mapping: (k2, j2, h2) ----
    const int k2 = tid / 20;
    const int r2 = tid % 20;
    const int j2 = r2 >> 1;
    const int h2 = r2 & 1;
    const bool act = (tid < 80);

    // ================= layer-1 projection: Y1 = lrelu(sum_hop X_hop W0_hop + b0) ====
    if (act) {
        const float4* W0q = reinterpret_cast<const float4*>(s_W0);
        float4 acc0 = make_float4(0.f, 0.f, 0.f, 0.f);
        float4 acc1 = make_float4(0.f, 0.f, 0.f, 0.f);
        #pragma unroll
        for (int hop = 0; hop < 4; hop++) {
            float4 xv = *reinterpret_cast<const float4*>(&s_x[SXW(hop, k2, j2)]);
            int base = hop * 12 + h2 * 2;
            acc0 = f4fma(xv.x, W0q[base + 0], acc0);
            acc1 = f4fma(xv.x, W0q[base + 1], acc1);
            acc0 = f4fma(xv.y, W0q[base + 4], acc0);
            acc1 = f4fma(xv.y, W0q[base + 5], acc1);
            acc0 = f4fma(xv.z, W0q[base + 8], acc0);
            acc1 = f4fma(xv.z, W0q[base + 9], acc1);
        }
        float4 bb0 = reinterpret_cast<const float4*>(s_b0)[h2 * 2];
        float4 bb1 = reinterpret_cast<const float4*>(s_b0)[h2 * 2 + 1];
        float4 v0 = make_float4(lrelu(acc0.x + bb0.x), lrelu(acc0.y + bb0.y),
                                lrelu(acc0.z + bb0.z), lrelu(acc0.w + bb0.w));
        float4 v1 = make_float4(lrelu(acc1.x + bb1.x), lrelu(acc1.y + bb1.y),
                                lrelu(acc1.z + bb1.z), lrelu(acc1.w + bb1.w));
        float* yr = &s_Y1[Y1W(k2, j2) + h2 * 8];
        reinterpret_cast<float4*>(yr)[0] = v0;
        reinterpret_cast<float4*>(yr)[1] = v1;
    }
    __syncthreads();

    // ================= layer-2, Horner form =================
    // z = H W3; z = A z + H W2; z = A z + H W1; z = A z + H W0
    const float4* W1q = reinterpret_cast<const float4*>(s_W1);
    float acol2[10];
    float4 y0, y1, y2, y3;
    float4 acc = make_float4(0.f, 0.f, 0.f, 0.f);
    if (act) {
        #pragma unroll
        for (int i = 0; i < 10; i++) acol2[i] = s_A[k2][i][j2];
        const float4* yq = reinterpret_cast<const float4*>(&s_Y1[Y1W(k2, j2)]);
        y0 = yq[0]; y1 = yq[1]; y2 = yq[2]; y3 = yq[3];
        acc = proj16(W1q, 3 * 32 + h2, y0, y1, y2, y3, acc);
        *reinterpret_cast<float4*>(&s_zA[ZW(k2, j2) + h2 * 4]) = acc;
    }
    __syncthreads();

    float* zsrc = s_zA;
    float* zdst = s_zB;
    #pragma unroll
    for (int hop = 2; hop >= 1; hop--) {
        if (act) {
            float4 agg = make_float4(0.f, 0.f, 0.f, 0.f);
            const float* zp = &zsrc[ZW(k2, 0) + h2 * 4];
            #pragma unroll
            for (int i = 0; i < 10; i++) {
                float4 zv = *reinterpret_cast<const float4*>(&zp[i * 12]);
                agg = f4fma(acol2[i], zv, agg);
            }
            agg = proj16(W1q, hop * 32 + h2, y0, y1, y2, y3, agg);
            *reinterpret_cast<float4*>(&zdst[ZW(k2, j2) + h2 * 4]) = agg;
        }
        __syncthreads();
        float* t = zsrc; zsrc = zdst; zdst = t;
    }
    if (act) {
        float4 agg = make_float4(0.f, 0.f, 0.f, 0.f);
        const float* zp = &zsrc[ZW(k2, 0) + h2 * 4];
        #pragma unroll
        for (int i = 0; i < 10; i++) {
            float4 zv = *reinterpret_cast<const float4*>(&zp[i * 12]);
            agg = f4fma(acol2[i], zv, agg);
        }
        agg = proj16(W1q, 0 * 32 + h2, y0, y1, y2, y3, agg);
        float4 bb = reinterpret_cast<const float4*>(s_b1)[h2];
        float4 v = make_float4(lrelu(agg.x + bb.x), lrelu(agg.y + bb.y),
                               lrelu(agg.z + bb.z), lrelu(agg.w + bb.w));
        reinterpret_cast<float4*>(s_y[k2][j2])[h2] = v;
    }
    __syncthreads();

    // ================= epilogue =================
    // yw = y @ w_w.T (quad of d per thread, same 80-thread mapping)
    if (act) {
        const float4* yv = reinterpret_cast<const float4*>(s_y[k2][j2]);
        float4 ya = yv[0], yb = yv[1];
        const float4* wwv = reinterpret_cast<const float4*>(s_ww);
        int d = h2 * 4;
        float4 r;
        r.x = dot4(ya, wwv[(d + 0) * 2]) + dot4(yb, wwv[(d + 0) * 2 + 1]);
        r.y = dot4(ya, wwv[(d + 1) * 2]) + dot4(yb, wwv[(d + 1) * 2 + 1]);
        r.z = dot4(ya, wwv[(d + 2) * 2]) + dot4(yb, wwv[(d + 2) * 2 + 1]);
        r.w = dot4(ya, wwv[(d + 3) * 2]) + dot4(yb, wwv[(d + 3) * 2 + 1]);
        reinterpret_cast<float4*>(s_yw[k2][j2])[h2] = r;
    }
    // a_ik, t_k
    if (tid < 40) {
        int k = tid / 10, j = tid % 10;
        const float4* yv = reinterpret_cast<const float4*>(s_y[k][j]);
        float4 ya = yv[0], yb = yv[1];
        const float4* bpv = reinterpret_cast<const float4*>(s_bp);
        const float4* cpv = reinterpret_cast<const float4*>(s_cp);
        float ay = dot4(ya, bpv[0]) + dot4(yb, bpv[1]);
        float ty = dot4(ya, cpv[0]) + dot4(yb, cpv[1]);
        out[OFF_AIK + (k * Bb + b) * 10 + j] = s_a0 + fmaxf(ay, 0.f);
        float tk = ty * (1.0f - s_pm[k][j]);
        if (tk == 0.0f) tk = -10000000000.0f;
        s_tk[k][j] = tk;
    }
    __syncthreads();

    // t_j = softmax over K
    if (tid < 10) {
        float t0 = s_tk[0][tid], t1 = s_tk[1][tid], t2 = s_tk[2][tid], t3 = s_tk[3][tid];
        float m = fmaxf(fmaxf(t0, t1), fmaxf(t2, t3));
        float e0 = __expf(t0 - m), e1 = __expf(t1 - m);
        float e2 = __expf(t2 - m), e3 = __expf(t3 - m);
        float inv = 1.f / (e0 + e1 + e2 + e3);
        out[OFF_TJ + (0 * Bb + b) * 10 + tid] = e0 * inv;
        out[OFF_TJ + (1 * Bb + b) * 10 + tid] = e1 * inv;
        out[OFF_TJ + (2 * Bb + b) * 10 + tid] = e2 * inv;
        out[OFF_TJ + (3 * Bb + b) * 10 + tid] = e3 * inv;
    }

    // K_y + softmax over K -> k_ij
    if (tid < 100) {
        int n = tid / 10, m = tid % 10;
        float kv[4];
        #pragma unroll
        for (int k = 0; k < 4; k++) {
            const float4* av = reinterpret_cast<const float4*>(s_yw[k][n]);
            const float4* cv = reinterpret_cast<const float4*>(s_y[k][m]);
            kv[k] = dot4(av[0], cv[0]) + dot4(av[1], cv[1]);
        }
        float mx = fmaxf(fmaxf(kv[0], kv[1]), fmaxf(kv[2], kv[3]));
        float e[4];
        float ssum = 0.f;
        #pragma unroll
        for (int k = 0; k < 4; k++) { e[k] = __expf(kv[k] - mx); ssum += e[k]; }
        float inv = 1.f / ssum;
        #pragma unroll
        for (int k = 0; k < 4; k++)
            out[OFF_KIJ + (k * Bb + b) * 100 + tid] = e[k] * inv;
    }
}

extern "C" void kernel_launch(void* const* d_in, const int* in_sizes, int n_in,
                              void* d_out, int out_size) {
    (void)out_size;
    const float* x  = (const float*)d_in[0];
    const float* ew = (const float*)d_in[2];
    int base = 3;
    if (n_in >= 15 && in_sizes[3] == 1 && in_sizes[4] == 1 && in_sizes[5] == 1) base = 6;
    const float* eigen = (const float*)d_in[base + 0];
    const float* a0    = (const float*)d_in[base + 1];
    const float* W0    = (const float*)d_in[base + 2];
    const float* b0    = (const float*)d_in[base + 3];
    const float* W1    = (const float*)d_in[base + 4];
    const float* b1    = (const float*)d_in[base + 5];
    const float* bp    = (const float*)d_in[base + 6];
    const float* cp    = (const float*)d_in[base + 7];
    const float* ww    = (const float*)d_in[base + 8];

    gnn_kernel<<<Bb, 128>>>(x, ew, eigen, a0, W0, b0, W1, b1, bp, cp, ww, (float*)d_out);
}

// round 5
// speedup vs baseline: 1.6838x; 1.0781x over previous
#include <cuda_runtime.h>

#define Bb 32768

#define OFF_KIJ 0
#define OFF_AIK 13107200
#define OFF_TJ  14417920
#define OFF_R   15728640
#define OFF_RT  28835840

static __device__ __forceinline__ int eidx(int i, int j) {
    return i * 9 + j - (j > i ? 1 : 0);
}
static __device__ __forceinline__ float4 f4fma(float a, float4 w, float4 acc) {
    acc.x = fmaf(a, w.x, acc.x);
    acc.y = fmaf(a, w.y, acc.y);
    acc.z = fmaf(a, w.z, acc.z);
    acc.w = fmaf(a, w.w, acc.w);
    return acc;
}
static __device__ __forceinline__ float dot4(float4 a, float4 b) {
    return a.x*b.x + a.y*b.y + a.z*b.z + a.w*b.w;
}
static __device__ __forceinline__ float lrelu(float v) {
    return v >= 0.f ? v : 0.01f * v;
}
// acc += (16-vec y) dot (16x4 slab of W1), W1 quads at base, stride 2 per c
static __device__ __forceinline__ float4 proj16(const float4* __restrict__ Wq, int base,
                                                float4 y0, float4 y1, float4 y2, float4 y3,
                                                float4 acc) {
    acc = f4fma(y0.x, Wq[base + 0],  acc);
    acc = f4fma(y0.y, Wq[base + 2],  acc);
    acc = f4fma(y0.z, Wq[base + 4],  acc);
    acc = f4fma(y0.w, Wq[base + 6],  acc);
    acc = f4fma(y1.x, Wq[base + 8],  acc);
    acc = f4fma(y1.y, Wq[base + 10], acc);
    acc = f4fma(y1.z, Wq[base + 12], acc);
    acc = f4fma(y1.w, Wq[base + 14], acc);
    acc = f4fma(y2.x, Wq[base + 16], acc);
    acc = f4fma(y2.y, Wq[base + 18], acc);
    acc = f4fma(y2.z, Wq[base + 20], acc);
    acc = f4fma(y2.w, Wq[base + 22], acc);
    acc = f4fma(y3.x, Wq[base + 24], acc);
    acc = f4fma(y3.y, Wq[base + 26], acc);
    acc = f4fma(y3.z, Wq[base + 28], acc);
    acc = f4fma(y3.w, Wq[base + 30], acc);
    return acc;
}

// word-offset helpers
#define SXW(h,k,j)  ((((h)*4+(k))*10+(j))*4)    // s_x  [hop][k][j][4]
#define Y1W(k,j)    ((k)*200+(j)*20)            // s_Y1 [k][j][20] (16 used)
#define ZW(k,j)     ((k)*120+(j)*12)            // s_z  [k][j][12] (8 used)

__global__ __launch_bounds__(128, 8) void gnn_kernel(
    const float* __restrict__ x,
    const float* __restrict__ ew,
    const float* __restrict__ eigen,
    const float* __restrict__ a0p,
    const float* __restrict__ W0,
    const float* __restrict__ b0,
    const float* __restrict__ W1,
    const float* __restrict__ b1,
    const float* __restrict__ bp,
    const float* __restrict__ cp,
    const float* __restrict__ ww,
    float* __restrict__ out)
{
    const int b = blockIdx.x;
    const int tid = threadIdx.x;

    __shared__ float s_w[4][90];
    __shared__ float s_dinv[4][10];
    __shared__ float s_A[4][10][10];
    __shared__ __align__(16) float s_x[640];    // hop-propagated inputs (3-wide, padded to 4)
    __shared__ __align__(16) float s_Y1[800];   // layer-1 output, rows padded to 20
    __shared__ __align__(16) float s_zA[480];   // Horner state ping
    __shared__ __align__(16) float s_zB[480];   // Horner state pong
    __shared__ __align__(16) float s_y[4][10][8];
    __shared__ __align__(16) float s_yw[4][10][8];
    __shared__ float s_pm[4][10];
    __shared__ float s_tk[4][10];
    __shared__ float s_eig[4];
    __shared__ __align__(16) float s_W0[192];   // [hop][3][16]
    __shared__ __align__(16) float s_W1[512];   // [hop][16][8]
    __shared__ __align__(16) float s_b0[16];
    __shared__ __align__(16) float s_b1[8];
    __shared__ __align__(16) float s_bp[8];
    __shared__ __align__(16) float s_cp[8];
    __shared__ __align__(16) float s_ww[64];
    __shared__ float s_a0;

    // ---- stage parameters ----
    for (int i = tid; i < 192; i += 128) s_W0[i] = W0[i];
    for (int i = tid; i < 512; i += 128) s_W1[i] = W1[i];
    if (tid < 16)                   s_b0[tid]      = b0[tid];
    else if (tid < 24)              s_b1[tid - 16] = b1[tid - 16];
    else if (tid < 32)              s_bp[tid - 24] = bp[tid - 24];
    else if (tid < 40)              s_cp[tid - 32] = cp[tid - 32];
    else if (tid == 40)             s_a0           = a0p[0];
    else if (tid >= 44 && tid < 48) s_eig[tid - 44] = eigen[(tid - 44) * Bb + b];
    if (tid >= 64) s_ww[tid - 64] = ww[tid - 64];

    {
        const float* ewb = ew + (size_t)b * 90;
        for (int idx = tid; idx < 360; idx += 128) {
            int k = idx / 90, e = idx % 90;
            s_w[k][e] = ewb[(size_t)k * (Bb * 90) + e];
        }
    }
    {
        const float* xb = x + (size_t)b * 30;
        for (int idx = tid; idx < 120; idx += 128) {
            int k = idx / 30, r = idx % 30;
            float v = xb[(size_t)k * (Bb * 30) + r];
            int j = r / 3, c = r % 3;
            s_x[(k * 10 + j) * 4 + c] = v;     // hop 0
            if (c == 2) s_pm[k][j] = fmaxf(v, 0.0f);
        }
    }
    __syncthreads();

    // ---- degree + dinv ----
    if (tid < 40) {
        int k = tid / 10, j = tid % 10;
        float d = 0.f;
        #pragma unroll
        for (int i = 0; i < 10; i++)
            if (i != j) d += s_w[k][eidx(i, j)];
        s_dinv[k][j] = (d > 0.f) ? rsqrtf(d) : 0.f;
    }
    __syncthreads();

    // ---- normalized adjacency + R / R_t : fixed (n,m) per thread, k unrolled ----
    if (tid < 100) {
        const int n = tid / 10, m = tid % 10;
        const bool diag = (n == m);
        const int e_nm = diag ? 0 : eidx(n, m);
        const int e_mn = diag ? 0 : eidx(m, n);
        float* outR  = out + OFF_R  + (size_t)b * 100 + tid;
        float* outRT = out + OFF_RT + (size_t)b * 100 + tid;
        #pragma unroll
        for (int k = 0; k < 4; k++) {
            float wnm = diag ? 0.f : s_w[k][e_nm];
            float wmn = diag ? 0.f : s_w[k][e_mn];
            s_A[k][n][m] = wnm * s_dinv[k][n] * s_dinv[k][m];
            float e = s_eig[k];
            outR [(size_t)k * (Bb * 100)] = wnm * e;
            outRT[(size_t)k * (Bb * 100)] = wmn * e;
        }
    }
    __syncthreads();

    // ================= layer-1 hop propagation (3-wide) =================
    const int k1 = tid / 30;
    const int r1 = tid % 30;
    const int j1 = r1 / 3;
    const int c1 = r1 % 3;
    float acol1[10];
    if (tid < 120) {
        #pragma unroll
        for (int i = 0; i < 10; i++) acol1[i] = s_A[k1][i][j1];
    }
    #pragma unroll
    for (int hk = 0; hk < 3; hk++) {
        if (tid < 120) {
            const float* src = &s_x[SXW(hk, k1, 0) + c1];
            float s = 0.f;
            #pragma unroll
            for (int i = 0; i < 10; i++) s = fmaf(acol1[i], src[i * 4], s);
            s_x[SXW(hk + 1, k1, j1) + c1] = s;
        }
        __syncthreads();
    }

    // ---- common 80-thread mapping: (k2, j2, h2) ----
    const int k2 = tid / 20;
    const int r2 = tid % 20;
    const int j2 = r2 >> 1;
    const int h2 = r2 & 1;
    const bool act = (tid < 80);

    // ================= layer-1 projection =================
    if (act) {
        const float4* W0q = reinterpret_cast<const float4*>(s_W0);
        float4 acc0 = make_float4(0.f, 0.f, 0.f, 0.f);
        float4 acc1 = make_float4(0.f, 0.f, 0.f, 0.f);
        #pragma unroll
        for (int hop = 0; hop < 4; hop++) {
            float4 xv = *reinterpret_cast<const float4*>(&s_x[SXW(hop, k2, j2)]);
            int base = hop * 12 + h2 * 2;
            acc0 = f4fma(xv.x, W0q[base + 0], acc0);
            acc1 = f4fma(xv.x, W0q[base + 1], acc1);
            acc0 = f4fma(xv.y, W0q[base + 4], acc0);
            acc1 = f4fma(xv.y, W0q[base + 5], acc1);
            acc0 = f4fma(xv.z, W0q[base + 8], acc0);
            acc1 = f4fma(xv.z, W0q[base + 9], acc1);
        }
        float4 bb0 = reinterpret_cast<const float4*>(s_b0)[h2 * 2];
        float4 bb1 = reinterpret_cast<const float4*>(s_b0)[h2 * 2 + 1];
        float4 v0 = make_float4(lrelu(acc0.x + bb0.x), lrelu(acc0.y + bb0.y),
                                lrelu(acc0.z + bb0.z), lrelu(acc0.w + bb0.w));
        float4 v1 = make_float4(lrelu(acc1.x + bb1.x), lrelu(acc1.y + bb1.y),
                                lrelu(acc1.z + bb1.z), lrelu(acc1.w + bb1.w));
        float* yr = &s_Y1[Y1W(k2, j2) + h2 * 8];
        reinterpret_cast<float4*>(yr)[0] = v0;
        reinterpret_cast<float4*>(yr)[1] = v1;
    }
    __syncthreads();

    // ================= layer-2, Horner form =================
    const float4* W1q = reinterpret_cast<const float4*>(s_W1);
    float acol2[10];
    float4 y0, y1, y2, y3;
    float4 acc = make_float4(0.f, 0.f, 0.f, 0.f);
    if (act) {
        #pragma unroll
        for (int i = 0; i < 10; i++) acol2[i] = s_A[k2][i][j2];
        const float4* yq = reinterpret_cast<const float4*>(&s_Y1[Y1W(k2, j2)]);
        y0 = yq[0]; y1 = yq[1]; y2 = yq[2]; y3 = yq[3];
        acc = proj16(W1q, 3 * 32 + h2, y0, y1, y2, y3, acc);
        *reinterpret_cast<float4*>(&s_zA[ZW(k2, j2) + h2 * 4]) = acc;
    }
    __syncthreads();

    float* zsrc = s_zA;
    float* zdst = s_zB;
    #pragma unroll
    for (int hop = 2; hop >= 1; hop--) {
        if (act) {
            float4 agg = make_float4(0.f, 0.f, 0.f, 0.f);
            const float* zp = &zsrc[ZW(k2, 0) + h2 * 4];
            #pragma unroll
            for (int i = 0; i < 10; i++) {
                float4 zv = *reinterpret_cast<const float4*>(&zp[i * 12]);
                agg = f4fma(acol2[i], zv, agg);
            }
            agg = proj16(W1q, hop * 32 + h2, y0, y1, y2, y3, agg);
            *reinterpret_cast<float4*>(&zdst[ZW(k2, j2) + h2 * 4]) = agg;
        }
        __syncthreads();
        float* t = zsrc; zsrc = zdst; zdst = t;
    }
    if (act) {
        float4 agg = make_float4(0.f, 0.f, 0.f, 0.f);
        const float* zp = &zsrc[ZW(k2, 0) + h2 * 4];
        #pragma unroll
        for (int i = 0; i < 10; i++) {
            float4 zv = *reinterpret_cast<const float4*>(&zp[i * 12]);
            agg = f4fma(acol2[i], zv, agg);
        }
        agg = proj16(W1q, 0 * 32 + h2, y0, y1, y2, y3, agg);
        float4 bb = reinterpret_cast<const float4*>(s_b1)[h2];
        float4 v = make_float4(lrelu(agg.x + bb.x), lrelu(agg.y + bb.y),
                               lrelu(agg.z + bb.z), lrelu(agg.w + bb.w));
        reinterpret_cast<float4*>(s_y[k2][j2])[h2] = v;
    }
    __syncthreads();

    // ================= epilogue =================
    if (act) {
        const float4* yv = reinterpret_cast<const float4*>(s_y[k2][j2]);
        float4 ya = yv[0], yb = yv[1];
        const float4* wwv = reinterpret_cast<const float4*>(s_ww);
        int d = h2 * 4;
        float4 r;
        r.x = dot4(ya, wwv[(d + 0) * 2]) + dot4(yb, wwv[(d + 0) * 2 + 1]);
        r.y = dot4(ya, wwv[(d + 1) * 2]) + dot4(yb, wwv[(d + 1) * 2 + 1]);
        r.z = dot4(ya, wwv[(d + 2) * 2]) + dot4(yb, wwv[(d + 2) * 2 + 1]);
        r.w = dot4(ya, wwv[(d + 3) * 2]) + dot4(yb, wwv[(d + 3) * 2 + 1]);
        reinterpret_cast<float4*>(s_yw[k2][j2])[h2] = r;
    }
    // a_ik, t_k
    if (tid < 40) {
        int k = tid / 10, j = tid % 10;
        const float4* yv = reinterpret_cast<const float4*>(s_y[k][j]);
        float4 ya = yv[0], yb = yv[1];
        const float4* bpv = reinterpret_cast<const float4*>(s_bp);
        const float4* cpv = reinterpret_cast<const float4*>(s_cp);
        float ay = dot4(ya, bpv[0]) + dot4(yb, bpv[1]);
        float ty = dot4(ya, cpv[0]) + dot4(yb, cpv[1]);
        out[OFF_AIK + (size_t)k * (Bb * 10) + (size_t)b * 10 + j] = s_a0 + fmaxf(ay, 0.f);
        float tk = ty * (1.0f - s_pm[k][j]);
        if (tk == 0.0f) tk = -10000000000.0f;
        s_tk[k][j] = tk;
    }
    __syncthreads();

    // t_j = softmax over K
    if (tid < 10) {
        float t0 = s_tk[0][tid], t1 = s_tk[1][tid], t2 = s_tk[2][tid], t3 = s_tk[3][tid];
        float m = fmaxf(fmaxf(t0, t1), fmaxf(t2, t3));
        float e0 = __expf(t0 - m), e1 = __expf(t1 - m);
        float e2 = __expf(t2 - m), e3 = __expf(t3 - m);
        float inv = 1.f / (e0 + e1 + e2 + e3);
        float* pt = out + OFF_TJ + (size_t)b * 10 + tid;
        pt[0]            = e0 * inv;
        pt[Bb * 10]      = e1 * inv;
        pt[2 * Bb * 10]  = e2 * inv;
        pt[3 * Bb * 10]  = e3 * inv;
    }

    // K_y + softmax over K -> k_ij
    if (tid < 100) {
        int n = tid / 10, m = tid % 10;
        float kv[4];
        #pragma unroll
        for (int k = 0; k < 4; k++) {
            const float4* av = reinterpret_cast<const float4*>(s_yw[k][n]);
            const float4* cv = reinterpret_cast<const float4*>(s_y[k][m]);
            kv[k] = dot4(av[0], cv[0]) + dot4(av[1], cv[1]);
        }
        float mx = fmaxf(fmaxf(kv[0], kv[1]), fmaxf(kv[2], kv[3]));
        float e[4];
        float ssum = 0.f;
        #pragma unroll
        for (int k = 0; k < 4; k++) { e[k] = __expf(kv[k] - mx); ssum += e[k]; }
        float inv = 1.f / ssum;
        float* pk = out + OFF_KIJ + (size_t)b * 100 + tid;
        #pragma unroll
        for (int k = 0; k < 4; k++)
            pk[(size_t)k * (Bb * 100)] = e[k] * inv;
    }
}

extern "C" void kernel_launch(void* const* d_in, const int* in_sizes, int n_in,
                              void* d_out, int out_size) {
    (void)out_size;
    const float* x  = (const float*)d_in[0];
    const float* ew = (const float*)d_in[2];
    int base = 3;
    if (n_in >= 15 && in_sizes[3] == 1 && in_sizes[4] == 1 && in_sizes[5] == 1) base = 6;
    const float* eigen = (const float*)d_in[base + 0];
    const float* a0    = (const float*)d_in[base + 1];
    const float* W0    = (const float*)d_in[base + 2];
    const float* b0    = (const float*)d_in[base + 3];
    const float* W1    = (const float*)d_in[base + 4];
    const float* b1    = (const float*)d_in[base + 5];
    const float* bp    = (const float*)d_in[base + 6];
    const float* cp    = (const float*)d_in[base + 7];
    const float* ww    = (const float*)d_in[base + 8];

    gnn_kernel<<<Bb, 128>>>(x, ew, eigen, a0, W0, b0, W1, b1, bp, cp, ww, (float*)d_out);
}